// round 1
// baseline (speedup 1.0000x reference)
#include <cuda_runtime.h>
#include <math.h>

#define S_ 128
#define B_ 16
#define E_ 512
#define H_ 512
#define V_ 32000

// ---------------- scratch (static device allocations; no cudaMalloc) ----------------
__device__ float g_x0 [S_ * B_ * E_];          // embedded input [s][b][E]
__device__ float g_xgf[S_ * B_ * 4 * H_];      // forward-gate preactivations [s][b][4H]
__device__ float g_xgb[S_ * B_ * 4 * H_];      // backward-gate preactivations
__device__ float g_y0 [S_ * B_ * 2 * H_];      // layer0 output [s][b][2H]
__device__ float g_y1 [S_ * B_ * 2 * H_];      // layer1 output
__device__ float g_h  [2][2][B_ * H_];         // [parity][dir][b*H + k]
__device__ unsigned int g_arrive = 0;          // monotonic grid-barrier ticket counter

// ---------------- helpers ----------------
__device__ __forceinline__ float sigf(float x) { return 1.f / (1.f + expf(-x)); }

__device__ __forceinline__ void grid_barrier(unsigned nb) {
    __syncthreads();
    if (threadIdx.x == 0) {
        __threadfence();
        unsigned t = atomicAdd(&g_arrive, 1u) + 1u;
        unsigned target = ((t + nb - 1u) / nb) * nb;
        while (atomicAdd(&g_arrive, 0u) < target) { __nanosleep(64); }
        __threadfence();
    }
    __syncthreads();
}

// ---------------- embedding: x0[s][b][:] = embed_w[ids[b][s]][:] ----------------
__global__ void embed_kernel(const int* __restrict__ ids,
                             const float* __restrict__ ew,
                             float* __restrict__ x0) {
    int row = blockIdx.x;               // row = s*B_ + b, 2048 rows
    int s = row >> 4, b = row & 15;
    int id = ids[b * S_ + s];
    const float4* src = (const float4*)(ew + (size_t)id * E_);
    float4* dst = (float4*)(x0 + (size_t)row * E_);
    dst[threadIdx.x] = src[threadIdx.x];   // 128 threads * float4 = 512 floats
}

// ---------------- generic strided SGEMM: C[m][n] = sum_k A[m][k]*B[n][k] + biases ----
// A: [M,K] row stride lda ; B: [N,K] row stride ldb ; C row stride ldc.
// Batched over blockIdx.z with element strides sA/sB/sC.
#define GBM 128
#define GBN 128
#define GBK 16

__global__ __launch_bounds__(256)
void gemm_tn_kernel(const float* __restrict__ A, int lda, long long sA,
                    const float* __restrict__ Bm, int ldb, long long sB,
                    float* __restrict__ C, int ldc, long long sC,
                    int M, int N, int K,
                    const float* __restrict__ bn1,
                    const float* __restrict__ bn2,
                    const float* __restrict__ bM) {
    __shared__ float As[GBK][GBM + 4];
    __shared__ float Bs[GBK][GBN + 4];

    const int bz = blockIdx.z;
    A  += (long long)bz * sA;
    Bm += (long long)bz * sB;
    C  += (long long)bz * sC;

    const int m0 = blockIdx.y * GBM;
    const int n0 = blockIdx.x * GBN;
    const int tid = threadIdx.x;
    const int tx = tid & 15;
    const int ty = tid >> 4;
    const int lrow = tid >> 2;          // 0..63
    const int lk   = (tid & 3) * 4;     // 0,4,8,12

    float acc[8][8];
#pragma unroll
    for (int i = 0; i < 8; i++)
#pragma unroll
        for (int j = 0; j < 8; j++) acc[i][j] = 0.f;

    const float* Ag = A  + (size_t)(m0 + lrow) * lda + lk;
    const float* Bg = Bm + (size_t)(n0 + lrow) * ldb + lk;
    const size_t aStep = (size_t)64 * lda;
    const size_t bStep = (size_t)64 * ldb;

    for (int kt = 0; kt < K; kt += GBK) {
        float4 a0 = *(const float4*)(Ag + kt);
        float4 a1 = *(const float4*)(Ag + aStep + kt);
        float4 b0 = *(const float4*)(Bg + kt);
        float4 b1 = *(const float4*)(Bg + bStep + kt);

        As[lk + 0][lrow] = a0.x; As[lk + 1][lrow] = a0.y;
        As[lk + 2][lrow] = a0.z; As[lk + 3][lrow] = a0.w;
        As[lk + 0][lrow + 64] = a1.x; As[lk + 1][lrow + 64] = a1.y;
        As[lk + 2][lrow + 64] = a1.z; As[lk + 3][lrow + 64] = a1.w;
        Bs[lk + 0][lrow] = b0.x; Bs[lk + 1][lrow] = b0.y;
        Bs[lk + 2][lrow] = b0.z; Bs[lk + 3][lrow] = b0.w;
        Bs[lk + 0][lrow + 64] = b1.x; Bs[lk + 1][lrow + 64] = b1.y;
        Bs[lk + 2][lrow + 64] = b1.z; Bs[lk + 3][lrow + 64] = b1.w;
        __syncthreads();

#pragma unroll
        for (int kk = 0; kk < GBK; kk++) {
            float ar[8], br[8];
            *(float4*)&ar[0] = *(const float4*)&As[kk][ty * 8];
            *(float4*)&ar[4] = *(const float4*)&As[kk][ty * 8 + 4];
            *(float4*)&br[0] = *(const float4*)&Bs[kk][tx * 8];
            *(float4*)&br[4] = *(const float4*)&Bs[kk][tx * 8 + 4];
#pragma unroll
            for (int i = 0; i < 8; i++)
#pragma unroll
                for (int j = 0; j < 8; j++)
                    acc[i][j] = fmaf(ar[i], br[j], acc[i][j]);
        }
        __syncthreads();
    }

    float bn[8];
#pragma unroll
    for (int j = 0; j < 8; j++) {
        int n = n0 + tx * 8 + j;
        float v = 0.f;
        if (bn1) v += bn1[n];
        if (bn2) v += bn2[n];
        bn[j] = v;
    }
#pragma unroll
    for (int i = 0; i < 8; i++) {
        int m = m0 + ty * 8 + i;
        float bm = bM ? bM[m] : 0.f;
        float* cp = C + (size_t)m * ldc + n0 + tx * 8;
        float4 v0, v1;
        v0.x = acc[i][0] + bn[0] + bm; v0.y = acc[i][1] + bn[1] + bm;
        v0.z = acc[i][2] + bn[2] + bm; v0.w = acc[i][3] + bn[3] + bm;
        v1.x = acc[i][4] + bn[4] + bm; v1.y = acc[i][5] + bn[5] + bm;
        v1.z = acc[i][6] + bn[6] + bm; v1.w = acc[i][7] + bn[7] + bm;
        *(float4*)cp = v0;
        *(float4*)(cp + 4) = v1;
    }
}

// ---------------- persistent bidirectional LSTM scan ----------------
// grid = 128 CTAs (dir(2) x batch(16) x kslice(4)), 128 threads each.
// Thread owns cell k of (dir,b): 4 Whh rows (i,f,g,o), c kept in a register.
__global__ __launch_bounds__(128)
void lstm_scan_kernel(const float* __restrict__ xgf,
                      const float* __restrict__ xgb,
                      const float* __restrict__ Whh_f,
                      const float* __restrict__ Whh_b,
                      float* __restrict__ y) {
    __shared__ float hs[H_];

    const int cta = blockIdx.x;
    const int dir = cta >> 6;           // 0 fwd, 1 bwd
    const int q   = cta & 63;
    const int b   = q >> 2;
    const int kq  = q & 3;
    const int k   = kq * 128 + threadIdx.x;   // 0..511

    const float* xg = dir ? xgb : xgf;
    const float* W  = dir ? Whh_b : Whh_f;

    const float4* w0 = (const float4*)(W + (size_t)(k         ) * H_);
    const float4* w1 = (const float4*)(W + (size_t)(k +  H_   ) * H_);
    const float4* w2 = (const float4*)(W + (size_t)(k + 2 * H_) * H_);
    const float4* w3 = (const float4*)(W + (size_t)(k + 3 * H_) * H_);
    const float4* hs4 = (const float4*)hs;

    float c_reg = 0.f;
    const unsigned nb = gridDim.x;

    for (int t = 0; t < S_; t++) {
        const int s = dir ? (S_ - 1 - t) : t;

        if (t > 0) {
            const float* hp = g_h[t & 1][dir] + b * H_;
#pragma unroll
            for (int r = 0; r < 4; r++)
                hs[threadIdx.x + r * 128] = hp[threadIdx.x + r * 128];
        }
        __syncthreads();

        const size_t base = (size_t)(s * B_ + b) * (4 * H_);
        float zi = xg[base + k];
        float zf = xg[base + H_ + k];
        float zg = xg[base + 2 * H_ + k];
        float zo = xg[base + 3 * H_ + k];

        if (t > 0) {
            float4 ai = {0.f,0.f,0.f,0.f}, af4 = {0.f,0.f,0.f,0.f};
            float4 ag4 = {0.f,0.f,0.f,0.f}, ao4 = {0.f,0.f,0.f,0.f};
#pragma unroll 8
            for (int qq = 0; qq < H_ / 4; qq++) {
                float4 hv = hs4[qq];
                float4 a;
                a = w0[qq];
                ai.x = fmaf(a.x, hv.x, ai.x); ai.y = fmaf(a.y, hv.y, ai.y);
                ai.z = fmaf(a.z, hv.z, ai.z); ai.w = fmaf(a.w, hv.w, ai.w);
                a = w1[qq];
                af4.x = fmaf(a.x, hv.x, af4.x); af4.y = fmaf(a.y, hv.y, af4.y);
                af4.z = fmaf(a.z, hv.z, af4.z); af4.w = fmaf(a.w, hv.w, af4.w);
                a = w2[qq];
                ag4.x = fmaf(a.x, hv.x, ag4.x); ag4.y = fmaf(a.y, hv.y, ag4.y);
                ag4.z = fmaf(a.z, hv.z, ag4.z); ag4.w = fmaf(a.w, hv.w, ag4.w);
                a = w3[qq];
                ao4.x = fmaf(a.x, hv.x, ao4.x); ao4.y = fmaf(a.y, hv.y, ao4.y);
                ao4.z = fmaf(a.z, hv.z, ao4.z); ao4.w = fmaf(a.w, hv.w, ao4.w);
            }
            zi += (ai.x + ai.y) + (ai.z + ai.w);
            zf += (af4.x + af4.y) + (af4.z + af4.w);
            zg += (ag4.x + ag4.y) + (ag4.z + ag4.w);
            zo += (ao4.x + ao4.y) + (ao4.z + ao4.w);
        }

        float ig = sigf(zi), fg = sigf(zf), og = sigf(zo);
        float gg = tanhf(zg);
        c_reg = fg * c_reg + ig * gg;
        float hh = og * tanhf(c_reg);

        g_h[(t + 1) & 1][dir][b * H_ + k] = hh;
        y[(size_t)(s * B_ + b) * (2 * H_) + dir * H_ + k] = hh;

        grid_barrier(nb);
    }
}

// ---------------- launch ----------------
extern "C" void kernel_launch(void* const* d_in, const int* in_sizes, int n_in,
                              void* d_out, int out_size) {
    const int*   ids   = (const int*)d_in[0];
    const float* embw  = (const float*)d_in[1];
    const float* Wih0f = (const float*)d_in[2];
    const float* Whh0f = (const float*)d_in[3];
    const float* bih0f = (const float*)d_in[4];
    const float* bhh0f = (const float*)d_in[5];
    const float* Wih0b = (const float*)d_in[6];
    const float* Whh0b = (const float*)d_in[7];
    const float* bih0b = (const float*)d_in[8];
    const float* bhh0b = (const float*)d_in[9];
    const float* Wih1f = (const float*)d_in[10];
    const float* Whh1f = (const float*)d_in[11];
    const float* bih1f = (const float*)d_in[12];
    const float* bhh1f = (const float*)d_in[13];
    const float* Wih1b = (const float*)d_in[14];
    const float* Whh1b = (const float*)d_in[15];
    const float* bih1b = (const float*)d_in[16];
    const float* bhh1b = (const float*)d_in[17];
    const float* lin_w = (const float*)d_in[18];
    const float* lin_b = (const float*)d_in[19];
    float* out = (float*)d_out;

    float *x0, *xgf, *xgb, *y0, *y1;
    cudaGetSymbolAddress((void**)&x0,  g_x0);
    cudaGetSymbolAddress((void**)&xgf, g_xgf);
    cudaGetSymbolAddress((void**)&xgb, g_xgb);
    cudaGetSymbolAddress((void**)&y0,  g_y0);
    cudaGetSymbolAddress((void**)&y1,  g_y1);

    const int M = S_ * B_;          // 2048 (s*B + b) rows

    // 1) embedding
    embed_kernel<<<M, 128>>>(ids, embw, x0);

    // 2) layer-0 input GEMMs: xg = x0 @ Wih^T + bih + bhh   (M=2048,N=2048,K=512)
    dim3 g0(2048 / GBN, M / GBM, 1);
    gemm_tn_kernel<<<g0, 256>>>(x0, E_, 0, Wih0f, E_, 0, xgf, 4 * H_, 0,
                                M, 4 * H_, E_, bih0f, bhh0f, nullptr);
    gemm_tn_kernel<<<g0, 256>>>(x0, E_, 0, Wih0b, E_, 0, xgb, 4 * H_, 0,
                                M, 4 * H_, E_, bih0b, bhh0b, nullptr);

    // 3) layer-0 scan -> y0
    lstm_scan_kernel<<<128, 128>>>(xgf, xgb, Whh0f, Whh0b, y0);

    // 4) layer-1 input GEMMs (K = 1024)
    gemm_tn_kernel<<<g0, 256>>>(y0, 2 * H_, 0, Wih1f, 2 * H_, 0, xgf, 4 * H_, 0,
                                M, 4 * H_, 2 * H_, bih1f, bhh1f, nullptr);
    gemm_tn_kernel<<<g0, 256>>>(y0, 2 * H_, 0, Wih1b, 2 * H_, 0, xgb, 4 * H_, 0,
                                M, 4 * H_, 2 * H_, bih1b, bhh1b, nullptr);

    // 5) layer-1 scan -> y1
    lstm_scan_kernel<<<128, 128>>>(xgf, xgb, Whh1f, Whh1b, y1);

    // 6) final projection, batched over b:
    //    out[b][v][s] = sum_k lin_w[v][k] * y1[s][b][k] + lin_b[v]
    //    A = lin_w [V,1024], B_b = y1 + b*1024 with row (s) stride 16*1024,
    //    C_b = out + b*V*S with ldc = S (contiguous in s).
    dim3 gf(S_ / GBN, V_ / GBM, B_);
    gemm_tn_kernel<<<gf, 256>>>(lin_w, 2 * H_, 0,
                                y1, B_ * 2 * H_, 2 * H_,
                                out, S_, (long long)V_ * S_,
                                V_, S_, 2 * H_,
                                nullptr, nullptr, lin_b);
}

// round 5
// speedup vs baseline: 1.0842x; 1.0842x over previous
#include <cuda_runtime.h>
#include <math.h>
#include <stdint.h>

#define S_ 128
#define B_ 16
#define E_ 512
#define H_ 512
#define V_ 32000

// ---------------- scratch (static device allocations) ----------------
__device__ float g_x0 [S_ * B_ * E_];
__device__ float g_xgf[S_ * B_ * 4 * H_];
__device__ float g_xgb[S_ * B_ * 4 * H_];
__device__ float g_y0 [S_ * B_ * 2 * H_];
__device__ float g_y1 [S_ * B_ * 2 * H_];
__device__ float g_h  [2][2][B_ * H_];
__device__ unsigned int g_arrive = 0;

// ---------------- helpers ----------------
__device__ __forceinline__ uint32_t smem_u32(const void* p) {
    uint32_t a;
    asm("{ .reg .u64 t; cvta.to.shared.u64 t, %1; cvt.u32.u64 %0, t; }" : "=r"(a) : "l"(p));
    return a;
}
__device__ __forceinline__ float sigf(float x) { return 1.f / (1.f + expf(-x)); }

__device__ __forceinline__ void grid_barrier(unsigned nb) {
    __syncthreads();
    if (threadIdx.x == 0) {
        __threadfence();
        unsigned t = atomicAdd(&g_arrive, 1u) + 1u;
        unsigned target = ((t + nb - 1u) / nb) * nb;
        while (atomicAdd(&g_arrive, 0u) < target) { __nanosleep(64); }
        __threadfence();
    }
    __syncthreads();
}

// tf32 split: hi = fp32 rounded to tf32 grid, lo = residual
__device__ __forceinline__ void split_bits(float v, uint32_t& hb, uint32_t& lb) {
    uint32_t u = __float_as_uint(v);
    hb = (u + 0x1000u) & 0xFFFFE000u;
    lb = __float_as_uint(v - __uint_as_float(hb));
}

__device__ __forceinline__ void mma168(float* c, const uint32_t* a, const uint32_t* b) {
    asm volatile(
        "mma.sync.aligned.m16n8k8.row.col.f32.tf32.tf32.f32 "
        "{%0,%1,%2,%3}, {%4,%5,%6,%7}, {%8,%9}, {%0,%1,%2,%3};"
        : "+f"(c[0]), "+f"(c[1]), "+f"(c[2]), "+f"(c[3])
        : "r"(a[0]), "r"(a[1]), "r"(a[2]), "r"(a[3]), "r"(b[0]), "r"(b[1]));
}

#define CP16(dst, src) \
    asm volatile("cp.async.ca.shared.global [%0], [%1], 16;" :: "r"(dst), "l"(src))
#define CP_COMMIT() asm volatile("cp.async.commit_group;" ::: "memory")
#define CP_WAIT1()  asm volatile("cp.async.wait_group 1;"  ::: "memory")

// ---------------- embedding ----------------
__global__ void embed_kernel(const int* __restrict__ ids,
                             const float* __restrict__ ew,
                             float* __restrict__ x0) {
    int row = blockIdx.x;               // row = s*B_ + b
    int s = row >> 4, b = row & 15;
    int id = ids[b * S_ + s];
    const float4* src = (const float4*)(ew + (size_t)id * E_);
    float4* dst = (float4*)(x0 + (size_t)row * E_);
    dst[threadIdx.x] = src[threadIdx.x];
}

// ---------------- mma.sync tf32x3 GEMM ----------------
// C[m][n] = sum_k A[m][k]*B[n][k] (+biases). 128x128 CTA tile, K chunk 32.
// Fragment-order smem layout (raw fp32), XOR-swizzled; tf32 split in registers.
// blockIdx.x = bz*ntN + nt, blockIdx.y = m-tile.
#define CHUNK_F 4096                        // floats per (mat,stage): 128 x 32
#define STAGE_F (2 * CHUNK_F)               // A + B
#define GEMM_SMEM (2 * STAGE_F * 4)         // bytes = 65536

__device__ __forceinline__ void issue_chunk(
    const float* __restrict__ A, int lda,
    const float* __restrict__ B, int ldb,
    int m0, int n0, int kt,
    uint32_t sa, uint32_t sb, int tid)
{
    const int r  = tid >> 2;      // 0..63
    const int ks = tid & 3;
#pragma unroll
    for (int it = 0; it < 2; it++) {
        const int m = it * 64 + r;
#pragma unroll
        for (int j4 = 0; j4 < 2; j4++) {
            const int k   = ks * 8 + j4 * 4;
            const int kk2 = ks * 2 + j4;
            // A: element (m,k) -> frag slot
            {
                const float* g = A + (size_t)(m0 + m) * lda + kt + k;
                int mi = m >> 4, half = (m >> 3) & 1, gg = m & 7;
                int ia = kk2 * 512 + mi * 64 + half * 32 + ((gg ^ kk2) << 2);
                CP16(sa + ia * 4, g);
            }
            // B: element (n,k) -> frag slot
            {
                const float* g = B + (size_t)(n0 + m) * ldb + kt + k;
                int ni = m >> 3, gc = m & 7;
                int ib = kk2 * 512 + ni * 32 + ((gc ^ kk2) << 2);
                CP16(sb + ib * 4, g);
            }
        }
    }
}

__global__ __launch_bounds__(256, 1)
void gemm_mma(const float* __restrict__ A, int lda,
              const float* __restrict__ B, int ldb, long long sB,
              float* __restrict__ C, int ldc, long long sC,
              int K, int ntN,
              const float* __restrict__ bn1, const float* __restrict__ bn2,
              const float* __restrict__ bM) {
    extern __shared__ __align__(128) float sm[];

    const int tid  = threadIdx.x;
    const int wid  = tid >> 5;
    const int lane = tid & 31;
    const int g    = lane >> 2;
    const int t    = lane & 3;
    const int wm   = wid >> 2;    // 0..1
    const int wn   = wid & 3;     // 0..3

    const int bx = blockIdx.x;
    const int bz = bx / ntN;
    const int n0 = (bx - bz * ntN) * 128;
    const int m0 = blockIdx.y * 128;
    const float* Bb = B + (long long)bz * sB;
    float* Cb = C + (long long)bz * sC;

    const uint32_t smb = smem_u32(sm);
    const int nk = K >> 5;

    float acc[4][4][4];
#pragma unroll
    for (int i = 0; i < 4; i++)
#pragma unroll
        for (int j = 0; j < 4; j++)
#pragma unroll
            for (int r = 0; r < 4; r++) acc[i][j][r] = 0.f;

    // prologue: chunks 0 and 1 in flight
    issue_chunk(A, lda, Bb, ldb, m0, n0, 0,  smb, smb + CHUNK_F * 4, tid);
    CP_COMMIT();
    issue_chunk(A, lda, Bb, ldb, m0, n0, 32, smb + STAGE_F * 4, smb + (STAGE_F + CHUNK_F) * 4, tid);
    CP_COMMIT();

    for (int k = 0; k < nk; k++) {
        const int p = k & 1;
        CP_WAIT1();
        __syncthreads();

        const float* sa = sm + p * STAGE_F;
        const float* sb = sa + CHUNK_F;

#pragma unroll
        for (int kk = 0; kk < 4; kk++) {
            const int k2a = kk * 2, k2b = kk * 2 + 1;
            const int oa = ((g ^ k2a) << 2) + t;
            const int ob = ((g ^ k2b) << 2) + t;

            uint32_t ah[4][4], al[4][4];
#pragma unroll
            for (int mi = 0; mi < 4; mi++) {
                const int mig = wm * 4 + mi;
                float r0 = sa[k2a * 512 + mig * 64 + oa];
                float r1 = sa[k2a * 512 + mig * 64 + 32 + oa];
                float r2 = sa[k2b * 512 + mig * 64 + ob];
                float r3 = sa[k2b * 512 + mig * 64 + 32 + ob];
                split_bits(r0, ah[mi][0], al[mi][0]);
                split_bits(r1, ah[mi][1], al[mi][1]);
                split_bits(r2, ah[mi][2], al[mi][2]);
                split_bits(r3, ah[mi][3], al[mi][3]);
            }
            uint32_t bh[4][2], bl[4][2];
#pragma unroll
            for (int ni = 0; ni < 4; ni++) {
                const int nig = wn * 4 + ni;
                float q0 = sb[k2a * 512 + nig * 32 + oa];
                float q1 = sb[k2b * 512 + nig * 32 + ob];
                split_bits(q0, bh[ni][0], bl[ni][0]);
                split_bits(q1, bh[ni][1], bl[ni][1]);
            }
#pragma unroll
            for (int mi = 0; mi < 4; mi++)
#pragma unroll
                for (int ni = 0; ni < 4; ni++) {
                    mma168(acc[mi][ni], ah[mi], bh[ni]);
                    mma168(acc[mi][ni], ah[mi], bl[ni]);
                    mma168(acc[mi][ni], al[mi], bh[ni]);
                }
        }

        __syncthreads();
        if (k + 2 < nk) {
            issue_chunk(A, lda, Bb, ldb, m0, n0, (k + 2) * 32,
                        smb + p * STAGE_F * 4, smb + (p * STAGE_F + CHUNK_F) * 4, tid);
        }
        CP_COMMIT();
    }

    // epilogue: bias + store (c0: row g, cols 2t/2t+1; c2/c3: row g+8)
    float eb[4][2];
#pragma unroll
    for (int ni = 0; ni < 4; ni++) {
        int n = n0 + wn * 32 + ni * 8 + 2 * t;
        float e0 = 0.f, e1 = 0.f;
        if (bn1) { e0 += bn1[n]; e1 += bn1[n + 1]; }
        if (bn2) { e0 += bn2[n]; e1 += bn2[n + 1]; }
        eb[ni][0] = e0; eb[ni][1] = e1;
    }
#pragma unroll
    for (int mi = 0; mi < 4; mi++) {
        int r0 = m0 + wm * 64 + mi * 16 + g;
        int r1 = r0 + 8;
        float bm0 = bM ? bM[r0] : 0.f;
        float bm1 = bM ? bM[r1] : 0.f;
#pragma unroll
        for (int ni = 0; ni < 4; ni++) {
            int col = n0 + wn * 32 + ni * 8 + 2 * t;
            float2 v0, v1;
            v0.x = acc[mi][ni][0] + eb[ni][0] + bm0;
            v0.y = acc[mi][ni][1] + eb[ni][1] + bm0;
            v1.x = acc[mi][ni][2] + eb[ni][0] + bm1;
            v1.y = acc[mi][ni][3] + eb[ni][1] + bm1;
            *(float2*)(Cb + (size_t)r0 * ldc + col) = v0;
            *(float2*)(Cb + (size_t)r1 * ldc + col) = v1;
        }
    }
}

// ---------------- persistent bidirectional LSTM scan ----------------
__global__ __launch_bounds__(128)
void lstm_scan_kernel(const float* __restrict__ xgf,
                      const float* __restrict__ xgb,
                      const float* __restrict__ Whh_f,
                      const float* __restrict__ Whh_b,
                      float* __restrict__ y) {
    __shared__ float hs[H_];

    const int cta = blockIdx.x;
    const int dir = cta >> 6;
    const int q   = cta & 63;
    const int b   = q >> 2;
    const int kq  = q & 3;
    const int k   = kq * 128 + threadIdx.x;

    const float* xg = dir ? xgb : xgf;
    const float* W  = dir ? Whh_b : Whh_f;

    const float4* w0 = (const float4*)(W + (size_t)(k         ) * H_);
    const float4* w1 = (const float4*)(W + (size_t)(k +  H_   ) * H_);
    const float4* w2 = (const float4*)(W + (size_t)(k + 2 * H_) * H_);
    const float4* w3 = (const float4*)(W + (size_t)(k + 3 * H_) * H_);
    const float4* hs4 = (const float4*)hs;

    float c_reg = 0.f;
    const unsigned nb = gridDim.x;

    for (int t = 0; t < S_; t++) {
        const int s = dir ? (S_ - 1 - t) : t;

        if (t > 0) {
            const float* hp = g_h[t & 1][dir] + b * H_;
#pragma unroll
            for (int r = 0; r < 4; r++)
                hs[threadIdx.x + r * 128] = hp[threadIdx.x + r * 128];
        }
        __syncthreads();

        const size_t base = (size_t)(s * B_ + b) * (4 * H_);
        float zi = xg[base + k];
        float zf = xg[base + H_ + k];
        float zg = xg[base + 2 * H_ + k];
        float zo = xg[base + 3 * H_ + k];

        if (t > 0) {
            float4 ai = {0.f,0.f,0.f,0.f}, af4 = {0.f,0.f,0.f,0.f};
            float4 ag4 = {0.f,0.f,0.f,0.f}, ao4 = {0.f,0.f,0.f,0.f};
#pragma unroll 8
            for (int qq = 0; qq < H_ / 4; qq++) {
                float4 hv = hs4[qq];
                float4 a;
                a = w0[qq];
                ai.x = fmaf(a.x, hv.x, ai.x); ai.y = fmaf(a.y, hv.y, ai.y);
                ai.z = fmaf(a.z, hv.z, ai.z); ai.w = fmaf(a.w, hv.w, ai.w);
                a = w1[qq];
                af4.x = fmaf(a.x, hv.x, af4.x); af4.y = fmaf(a.y, hv.y, af4.y);
                af4.z = fmaf(a.z, hv.z, af4.z); af4.w = fmaf(a.w, hv.w, af4.w);
                a = w2[qq];
                ag4.x = fmaf(a.x, hv.x, ag4.x); ag4.y = fmaf(a.y, hv.y, ag4.y);
                ag4.z = fmaf(a.z, hv.z, ag4.z); ag4.w = fmaf(a.w, hv.w, ag4.w);
                a = w3[qq];
                ao4.x = fmaf(a.x, hv.x, ao4.x); ao4.y = fmaf(a.y, hv.y, ao4.y);
                ao4.z = fmaf(a.z, hv.z, ao4.z); ao4.w = fmaf(a.w, hv.w, ao4.w);
            }
            zi += (ai.x + ai.y) + (ai.z + ai.w);
            zf += (af4.x + af4.y) + (af4.z + af4.w);
            zg += (ag4.x + ag4.y) + (ag4.z + ag4.w);
            zo += (ao4.x + ao4.y) + (ao4.z + ao4.w);
        }

        float ig = sigf(zi), fg = sigf(zf), og = sigf(zo);
        float gg = tanhf(zg);
        c_reg = fg * c_reg + ig * gg;
        float hh = og * tanhf(c_reg);

        g_h[(t + 1) & 1][dir][b * H_ + k] = hh;
        y[(size_t)(s * B_ + b) * (2 * H_) + dir * H_ + k] = hh;

        grid_barrier(nb);
    }
}

// ---------------- launch ----------------
extern "C" void kernel_launch(void* const* d_in, const int* in_sizes, int n_in,
                              void* d_out, int out_size) {
    const int*   ids   = (const int*)d_in[0];
    const float* embw  = (const float*)d_in[1];
    const float* Wih0f = (const float*)d_in[2];
    const float* Whh0f = (const float*)d_in[3];
    const float* bih0f = (const float*)d_in[4];
    const float* bhh0f = (const float*)d_in[5];
    const float* Wih0b = (const float*)d_in[6];
    const float* Whh0b = (const float*)d_in[7];
    const float* bih0b = (const float*)d_in[8];
    const float* bhh0b = (const float*)d_in[9];
    const float* Wih1f = (const float*)d_in[10];
    const float* Whh1f = (const float*)d_in[11];
    const float* bih1f = (const float*)d_in[12];
    const float* bhh1f = (const float*)d_in[13];
    const float* Wih1b = (const float*)d_in[14];
    const float* Whh1b = (const float*)d_in[15];
    const float* bih1b = (const float*)d_in[16];
    const float* bhh1b = (const float*)d_in[17];
    const float* lin_w = (const float*)d_in[18];
    const float* lin_b = (const float*)d_in[19];
    float* out = (float*)d_out;

    float *x0, *xgf, *xgb, *y0, *y1;
    cudaGetSymbolAddress((void**)&x0,  g_x0);
    cudaGetSymbolAddress((void**)&xgf, g_xgf);
    cudaGetSymbolAddress((void**)&xgb, g_xgb);
    cudaGetSymbolAddress((void**)&y0,  g_y0);
    cudaGetSymbolAddress((void**)&y1,  g_y1);

    cudaFuncSetAttribute(gemm_mma, cudaFuncAttributeMaxDynamicSharedMemorySize, GEMM_SMEM);

    const int M = S_ * B_;   // 2048

    // 1) embedding
    embed_kernel<<<M, 128>>>(ids, embw, x0);

    // 2) layer-0 input GEMMs: xg = x0 @ Wih^T + bih + bhh  (M=2048,N=2048,K=512)
    dim3 g0(16, M / 128);
    gemm_mma<<<g0, 256, GEMM_SMEM>>>(x0, E_, Wih0f, E_, 0, xgf, 4 * H_, 0,
                                     E_, 16, bih0f, bhh0f, nullptr);
    gemm_mma<<<g0, 256, GEMM_SMEM>>>(x0, E_, Wih0b, E_, 0, xgb, 4 * H_, 0,
                                     E_, 16, bih0b, bhh0b, nullptr);

    // 3) layer-0 scan -> y0
    lstm_scan_kernel<<<128, 128>>>(xgf, xgb, Whh0f, Whh0b, y0);

    // 4) layer-1 input GEMMs (K = 1024)
    gemm_mma<<<g0, 256, GEMM_SMEM>>>(y0, 2 * H_, Wih1f, 2 * H_, 0, xgf, 4 * H_, 0,
                                     2 * H_, 16, bih1f, bhh1f, nullptr);
    gemm_mma<<<g0, 256, GEMM_SMEM>>>(y0, 2 * H_, Wih1b, 2 * H_, 0, xgb, 4 * H_, 0,
                                     2 * H_, 16, bih1b, bhh1b, nullptr);

    // 5) layer-1 scan -> y1
    lstm_scan_kernel<<<128, 128>>>(xgf, xgb, Whh1f, Whh1b, y1);

    // 6) final projection: out[b][v][s] = lin_w[v] . y1[s][b] + lin_b[v]
    //    A = lin_w [V,1024]; B rows (n=s) at y1 + b*1024, row stride 16*1024;
    //    C_b = out + b*V*S, ldc = S. grid.x = 16 batches (wave-adjacent lin_w reuse).
    dim3 gf(16, V_ / 128);
    gemm_mma<<<gf, 256, GEMM_SMEM>>>(lin_w, 2 * H_,
                                     y1, B_ * 2 * H_, 2 * H_,
                                     out, S_, (long long)V_ * S_,
                                     2 * H_, 1, nullptr, nullptr, lin_b);
}